// round 1
// baseline (speedup 1.0000x reference)
#include <cuda_runtime.h>

#define NN 100000
#define EE 600000
#define RR 3
#define FIN 128
#define FOUT 64

// ---------------- scratch (device globals; no allocation allowed) ----------
__device__ float g_hw[(size_t)RR * NN * FOUT];   // x @ W per relation  (76.8 MB)
__device__ float g_deg[RR * NN];
__device__ float g_dinv[RR * NN];

// ---------------- helpers --------------------------------------------------
__device__ __forceinline__ void red_add_v2(float* p, float a, float b) {
    asm volatile("red.global.add.v2.f32 [%0], {%1, %2};" :: "l"(p), "f"(a), "f"(b) : "memory");
}
__device__ __forceinline__ void ffma2(unsigned long long& acc, unsigned long long a, unsigned long long b) {
    asm("fma.rn.f32x2 %0, %1, %2, %0;" : "+l"(acc) : "l"(a), "l"(b));
}

// 1) deg := 1 (self loop), zero summary region
__global__ void k_init(float* __restrict__ out_sum) {
    int i = blockIdx.x * blockDim.x + threadIdx.x;
    if (i < RR * NN) g_deg[i] = 1.0f;
    if (i < RR * FOUT) out_sum[i] = 0.0f;
}

// 2) count in-degrees over dst
__global__ void k_count(const int* __restrict__ ei) {
    int i = blockIdx.x * blockDim.x + threadIdx.x;
    if (i >= RR * EE) return;
    int r = i / EE, e = i - r * EE;
    int d = ei[(size_t)r * 2 * EE + EE + e];
    atomicAdd(&g_deg[r * NN + d], 1.0f);
}

// 3) dinv = rsqrt(deg)   (deg >= 1 always)
__global__ void k_dinv() {
    int i = blockIdx.x * blockDim.x + threadIdx.x;
    if (i < RR * NN) g_dinv[i] = rsqrtf(g_deg[i]);
}

// 4) GEMM: g_hw[r] = x @ W[r].  Tile: 64 rows x 64 cols x K=128.
//    f32x2 packed FMA vectorized over K (k-split accumulator, horizontal add at end).
//    smem: xs = 64x128 f32 (natural row-major -> k-pairs are aligned float2),
//          wst = transposed W as float2 pairs wst[c][k2], pitch 65 to kill conflicts.
#define GEMM_TM 64
#define GEMM_XS_BYTES (GEMM_TM * FIN * 4)                 // 32768
#define GEMM_W_BYTES  (FOUT * 65 * 8)                     // 33280
#define GEMM_SMEM     (GEMM_XS_BYTES + GEMM_W_BYTES)      // 66048

__global__ void __launch_bounds__(256, 2) k_gemm(const float* __restrict__ x,
                                                 const float* __restrict__ Ws) {
    extern __shared__ char smem[];
    float* xs = (float*)smem;
    float2* wst = (float2*)(smem + GEMM_XS_BYTES);

    const int r = blockIdx.y;
    const int row0 = blockIdx.x * GEMM_TM;
    const int tid = threadIdx.x;
    const int nrows = min(GEMM_TM, NN - row0);

    // stage W transposed into pairs: wst[c*65 + k2] = (W[2k2][c], W[2k2+1][c])
    const float* W = Ws + (size_t)r * FIN * FOUT;
    for (int idx = tid; idx < FOUT * 64; idx += 256) {
        int cc = idx & 63, k2 = idx >> 6;
        float2 v;
        v.x = W[(2 * k2) * FOUT + cc];
        v.y = W[(2 * k2) * FOUT + FOUT + cc];
        wst[cc * 65 + k2] = v;
    }
    // stage x tile (flat float4 copy, coalesced, conflict-free)
    {
        const float4* src = (const float4*)(x + (size_t)row0 * FIN);
        float4* dst4 = (float4*)xs;
        int total4 = nrows * (FIN / 4);
        for (int idx = tid; idx < total4; idx += 256) dst4[idx] = src[idx];
    }
    __syncthreads();

    const int c = tid & 63;        // output column
    const int rg = tid >> 6;       // 0..3, owns rows rg*16 .. rg*16+15
    const unsigned long long* xs8 = (const unsigned long long*)xs;   // [row][k2]
    const unsigned long long* w8 = (const unsigned long long*)wst;   // pitch 65

    unsigned long long acc[16];
#pragma unroll
    for (int j = 0; j < 16; j++) acc[j] = 0ull;

#pragma unroll 2
    for (int k2 = 0; k2 < 64; k2++) {
        unsigned long long wv = w8[c * 65 + k2];
#pragma unroll
        for (int j = 0; j < 16; j++) {
            unsigned long long xv = xs8[(rg * 16 + j) * 64 + k2];   // broadcast LDS.64
            ffma2(acc[j], xv, wv);
        }
    }

    float* dst = g_hw + ((size_t)r * NN + row0) * FOUT;
#pragma unroll
    for (int j = 0; j < 16; j++) {
        int row = rg * 16 + j;
        if (row < nrows) {
            float2 f = *(float2*)&acc[j];
            dst[(size_t)row * FOUT + c] = f.x + f.y;   // merge k-split halves
        }
    }
}

// 5) init outputs with self-loop term: pos = hw[i]*dinv^2, neg = hw[perm[i]]*dinv^2
__global__ void k_initout(const int* __restrict__ perms,
                          float* __restrict__ out_pos, float* __restrict__ out_neg) {
    int idx = blockIdx.x * blockDim.x + threadIdx.x;      // over RR*NN*FOUT
    if (idx >= RR * NN * FOUT) return;
    int c = idx & 63;
    int ri = idx >> 6;                                    // = r*NN + i
    int r = ri / NN;
    float di = g_dinv[ri];
    float w2 = di * di;
    out_pos[idx] = g_hw[idx] * w2;
    int p = perms[ri];
    out_neg[idx] = g_hw[((size_t)r * NN + p) * FOUT + c] * w2;
}

// 6) edge scatter: one warp per edge, handles pos AND neg with red.v2.f32
__global__ void k_scatter(const int* __restrict__ ei, const int* __restrict__ perms,
                          float* __restrict__ out_pos, float* __restrict__ out_neg) {
    int gw = (blockIdx.x * blockDim.x + threadIdx.x) >> 5;
    int lane = threadIdx.x & 31;
    if (gw >= RR * EE) return;
    int r = gw / EE, e = gw - r * EE;
    const int* base = ei + (size_t)r * 2 * EE;
    int s = base[e];
    int d = base[EE + e];
    float w = g_dinv[r * NN + s] * g_dinv[r * NN + d];
    int ps = perms[r * NN + s];

    const float* hwr = g_hw + (size_t)r * NN * FOUT;
    float2 a = *((const float2*)(hwr + (size_t)s  * FOUT) + lane);
    float2 b = *((const float2*)(hwr + (size_t)ps * FOUT) + lane);

    size_t o = ((size_t)r * NN + d) * FOUT + lane * 2;
    red_add_v2(out_pos + o, a.x * w, a.y * w);
    red_add_v2(out_neg + o, b.x * w, b.y * w);
}

// 7) relu + bias on pos/neg, accumulate column sums for summary
#define FIN_ROWS 128
__global__ void k_final(const float* __restrict__ bs,
                        float* __restrict__ out_pos, float* __restrict__ out_neg,
                        float* __restrict__ out_sum) {
    __shared__ float sh[256];
    int r = blockIdx.y;
    int row0 = blockIdx.x * FIN_ROWS;
    int tid = threadIdx.x;
    int c = tid & 63, rq = tid >> 6;
    float b = bs[r * FOUT + c];
    float acc = 0.0f;
    size_t base = (size_t)r * NN * FOUT;
    int rend = min(row0 + FIN_ROWS, NN);
    for (int i = row0 + rq; i < rend; i += 4) {
        size_t k = base + (size_t)i * FOUT + c;
        float vp = fmaxf(out_pos[k] + b, 0.0f);
        out_pos[k] = vp;
        acc += vp;
        float vn = fmaxf(out_neg[k] + b, 0.0f);
        out_neg[k] = vn;
    }
    sh[tid] = acc;
    __syncthreads();
    if (rq == 0) {
        float t = sh[c] + sh[64 + c] + sh[128 + c] + sh[192 + c];
        atomicAdd(&out_sum[r * FOUT + c], t);
    }
}

// 8) summaries /= N
__global__ void k_scale(float* __restrict__ out_sum) {
    int i = threadIdx.x;
    if (i < RR * FOUT) out_sum[i] *= (1.0f / NN);
}

// ---------------- launch ----------------------------------------------------
extern "C" void kernel_launch(void* const* d_in, const int* in_sizes, int n_in,
                              void* d_out, int out_size) {
    const float* x     = (const float*)d_in[0];
    const int*   ei    = (const int*)d_in[1];
    const int*   perms = (const int*)d_in[2];
    const float* Ws    = (const float*)d_in[3];
    const float* bs    = (const float*)d_in[4];

    float* out = (float*)d_out;
    float* out_pos = out;
    float* out_neg = out + (size_t)RR * NN * FOUT;
    float* out_sum = out + (size_t)2 * RR * NN * FOUT;

    cudaFuncSetAttribute(k_gemm, cudaFuncAttributeMaxDynamicSharedMemorySize, GEMM_SMEM);

    k_init<<<(RR * NN + 255) / 256, 256>>>(out_sum);
    k_count<<<(RR * EE + 255) / 256, 256>>>(ei);
    k_dinv<<<(RR * NN + 255) / 256, 256>>>();
    k_gemm<<<dim3((NN + GEMM_TM - 1) / GEMM_TM, RR), 256, GEMM_SMEM>>>(x, Ws);
    k_initout<<<(RR * NN * FOUT + 255) / 256, 256>>>(perms, out_pos, out_neg);
    k_scatter<<<(RR * EE * 32 + 255) / 256, 256>>>(ei, perms, out_pos, out_neg);
    k_final<<<dim3((NN + FIN_ROWS - 1) / FIN_ROWS, RR), 256>>>(bs, out_pos, out_neg, out_sum);
    k_scale<<<1, 256>>>(out_sum);
}

// round 2
// speedup vs baseline: 1.7456x; 1.7456x over previous
#include <cuda_runtime.h>

#define NN 100000
#define EE 600000
#define RR 3
#define FIN 128
#define FOUT 64
#define M_ROWS (RR * NN)          // 300000

// ---------------- scratch (device globals; no allocation allowed) ----------
__device__ float g_hw[(size_t)RR * NN * FOUT];   // x @ W per relation (76.8 MB)
__device__ float g_dinv[M_ROWS];
__device__ int   g_cnt[M_ROWS];                  // in-degree (edges only)
__device__ int   g_cur[M_ROWS];                  // fill cursors
__device__ int   g_off[M_ROWS];                  // CSR row offsets (exclusive scan)
__device__ int   g_csr_src[RR * EE];             // CSR source ids
__device__ int   g_part[256];                    // scan partials

__device__ __forceinline__ void ffma2(unsigned long long& acc, unsigned long long a, unsigned long long b) {
    asm("fma.rn.f32x2 %0, %1, %2, %0;" : "+l"(acc) : "l"(a), "l"(b));
}

// 1) zero counts, cursors, summary
__global__ void k_init(float* __restrict__ out_sum) {
    int i = blockIdx.x * blockDim.x + threadIdx.x;
    if (i < M_ROWS) { g_cnt[i] = 0; g_cur[i] = 0; }
    if (i < RR * FOUT) out_sum[i] = 0.0f;
}

// 2) count in-degrees over dst
__global__ void k_count(const int* __restrict__ ei) {
    int i = blockIdx.x * blockDim.x + threadIdx.x;
    if (i >= RR * EE) return;
    int r = i / EE, e = i - r * EE;
    int d = ei[(size_t)r * 2 * EE + EE + e];
    atomicAdd(&g_cnt[r * NN + d], 1);
}

// 3) dinv = rsqrt(deg+1)  (self loop)
__global__ void k_dinv() {
    int i = blockIdx.x * blockDim.x + threadIdx.x;
    if (i < M_ROWS) g_dinv[i] = rsqrtf((float)(g_cnt[i] + 1));
}

// ---- exclusive scan of g_cnt -> g_off, 2048 elems/block --------------------
#define SCAN_NB ((M_ROWS + 2047) / 2048)   // 147
__global__ void k_scan1() {
    __shared__ int sh[512];
    int b = blockIdx.x, tid = threadIdx.x;
    int base = b * 2048 + tid * 4;
    int v[4], s = 0;
#pragma unroll
    for (int j = 0; j < 4; j++) { int idx = base + j; v[j] = (idx < M_ROWS) ? g_cnt[idx] : 0; s += v[j]; }
    sh[tid] = s; __syncthreads();
    for (int o = 1; o < 512; o <<= 1) {
        int t = (tid >= o) ? sh[tid - o] : 0;
        __syncthreads();
        sh[tid] += t;
        __syncthreads();
    }
    int run = sh[tid] - s;
#pragma unroll
    for (int j = 0; j < 4; j++) { int idx = base + j; if (idx < M_ROWS) g_off[idx] = run; run += v[j]; }
    if (tid == 511) g_part[b] = sh[511];
}
__global__ void k_scan2(int n) {
    __shared__ int sh[256];
    int tid = threadIdx.x;
    int v = (tid < n) ? g_part[tid] : 0;
    sh[tid] = v; __syncthreads();
    for (int o = 1; o < 256; o <<= 1) {
        int t = (tid >= o) ? sh[tid - o] : 0;
        __syncthreads();
        sh[tid] += t;
        __syncthreads();
    }
    if (tid < n) g_part[tid] = sh[tid] - v;
}
__global__ void k_scan3() {
    int i = blockIdx.x * blockDim.x + threadIdx.x;
    if (i < M_ROWS) g_off[i] += g_part[i >> 11];
}

// 4) fill CSR
__global__ void k_fill(const int* __restrict__ ei) {
    int i = blockIdx.x * blockDim.x + threadIdx.x;
    if (i >= RR * EE) return;
    int r = i / EE, e = i - r * EE;
    const int* base = ei + (size_t)r * 2 * EE;
    int s = base[e];
    int d = base[EE + e];
    int g = r * NN + d;
    int p = g_off[g] + atomicAdd(&g_cur[g], 1);
    g_csr_src[p] = s;
}

// 5) GEMM: g_hw[r] = x @ W[r].  Block: 256 thr, tile 128 rows x 64 cols.
//    Thread (tx 0..15, ty 0..15): 8 rows (ty*8..+7) x 4 cols (tx + 16j).
//    f32x2 packed FMA, k-split accumulators.
#define GT_M 128
#define XS_PITCH 65   // in ull (8B) units; 8*65 % 16 != 0 -> bank-safe row broadcast
#define GEMM_XS_BYTES (GT_M * XS_PITCH * 8)     // 66560
#define GEMM_W_BYTES  (64 * 64 * 8)             // 32768
#define GEMM_SMEM     (GEMM_XS_BYTES + GEMM_W_BYTES)

__global__ void __launch_bounds__(256, 2) k_gemm(const float* __restrict__ x,
                                                 const float* __restrict__ Ws) {
    extern __shared__ char smem[];
    unsigned long long* xs = (unsigned long long*)smem;                         // [128][65]
    unsigned long long* ws = (unsigned long long*)(smem + GEMM_XS_BYTES);       // [k2 64][c 64]

    const int r = blockIdx.y;
    const int row0 = blockIdx.x * GT_M;
    const int tid = threadIdx.x;
    const int nrows = min(GT_M, NN - row0);

    // stage W: ws[k2*64 + c] = (W[2k2][c], W[2k2+1][c])
    const float* W = Ws + (size_t)r * FIN * FOUT;
    for (int idx = tid; idx < 64 * 64; idx += 256) {
        int k2 = idx >> 6, c = idx & 63;
        float2 v;
        v.x = W[(2 * k2) * FOUT + c];
        v.y = W[(2 * k2) * FOUT + FOUT + c];
        ((float2*)ws)[idx] = v;
    }
    // stage x tile into pitched smem
    for (int idx = tid; idx < nrows * 32; idx += 256) {
        int row = idx >> 5, q = idx & 31;
        float4 v = *(const float4*)(x + ((size_t)(row0 + row)) * FIN + q * 4);
        float2* dst = (float2*)(xs + (size_t)row * XS_PITCH) + q * 2;
        dst[0] = make_float2(v.x, v.y);
        dst[1] = make_float2(v.z, v.w);
    }
    __syncthreads();

    const int tx = tid & 15;
    const int rbase = (tid >> 4) * 8;

    unsigned long long acc[8][4];
#pragma unroll
    for (int i = 0; i < 8; i++)
#pragma unroll
        for (int j = 0; j < 4; j++) acc[i][j] = 0ull;

#pragma unroll 2
    for (int k2 = 0; k2 < 64; k2++) {
        unsigned long long wv0 = ws[k2 * 64 + tx];
        unsigned long long wv1 = ws[k2 * 64 + tx + 16];
        unsigned long long wv2 = ws[k2 * 64 + tx + 32];
        unsigned long long wv3 = ws[k2 * 64 + tx + 48];
#pragma unroll
        for (int i = 0; i < 8; i++) {
            unsigned long long xv = xs[(rbase + i) * XS_PITCH + k2];
            ffma2(acc[i][0], xv, wv0);
            ffma2(acc[i][1], xv, wv1);
            ffma2(acc[i][2], xv, wv2);
            ffma2(acc[i][3], xv, wv3);
        }
    }

    float* dst = g_hw + ((size_t)r * NN + row0) * FOUT;
#pragma unroll
    for (int i = 0; i < 8; i++) {
        int row = rbase + i;
        if (row < nrows) {
#pragma unroll
            for (int j = 0; j < 4; j++) {
                float2 f = *(float2*)&acc[i][j];
                dst[(size_t)row * FOUT + tx + 16 * j] = f.x + f.y;
            }
        }
    }
}

// 6) fused gather: per dst row, sum messages (pos: hw[s], neg: hw[perm[s]]),
//    + self loop, + bias, relu, write out, accumulate summary column sums.
#define GB 1024
__global__ void __launch_bounds__(256) k_gather(const int* __restrict__ perms,
                                                const float* __restrict__ bs,
                                                float* __restrict__ out_pos,
                                                float* __restrict__ out_neg,
                                                float* __restrict__ out_sum) {
    __shared__ float ssum[FOUT];
    const int r = blockIdx.y;
    const int tid = threadIdx.x;
    if (tid < FOUT) ssum[tid] = 0.0f;
    __syncthreads();

    const int wid = tid >> 5, lane = tid & 31;
    const int half = lane >> 4, l = lane & 15;
    const float* hwr = g_hw + (size_t)r * NN * FOUT;
    float* outb = half ? out_neg : out_pos;
    const float4 b4 = *(const float4*)(bs + r * FOUT + l * 4);

    float4 asum = make_float4(0.f, 0.f, 0.f, 0.f);

    for (int row = blockIdx.x * 8 + wid; row < NN; row += GB * 8) {
        int g = r * NN + row;
        float dd = g_dinv[g];
        int self_s = half ? perms[g] : row;
        float4 v = *(const float4*)(hwr + (size_t)self_s * FOUT + l * 4);
        float w0 = dd * dd;
        float4 acc = make_float4(v.x * w0, v.y * w0, v.z * w0, v.w * w0);

        int beg = g_off[g];
        int end = beg + g_cnt[g];
        for (int e = beg; e < end; e++) {
            int s = g_csr_src[e];
            float w = g_dinv[r * NN + s] * dd;
            int src2 = half ? perms[r * NN + s] : s;
            float4 u = *(const float4*)(hwr + (size_t)src2 * FOUT + l * 4);
            acc.x += u.x * w; acc.y += u.y * w; acc.z += u.z * w; acc.w += u.w * w;
        }
        acc.x = fmaxf(acc.x + b4.x, 0.0f);
        acc.y = fmaxf(acc.y + b4.y, 0.0f);
        acc.z = fmaxf(acc.z + b4.z, 0.0f);
        acc.w = fmaxf(acc.w + b4.w, 0.0f);
        *(float4*)(outb + (size_t)g * FOUT + l * 4) = acc;
        if (!half) {
            asum.x += acc.x; asum.y += acc.y; asum.z += acc.z; asum.w += acc.w;
        }
    }
    if (!half) {
        atomicAdd(&ssum[l * 4 + 0], asum.x);
        atomicAdd(&ssum[l * 4 + 1], asum.y);
        atomicAdd(&ssum[l * 4 + 2], asum.z);
        atomicAdd(&ssum[l * 4 + 3], asum.w);
    }
    __syncthreads();
    if (tid < FOUT) atomicAdd(&out_sum[r * FOUT + tid], ssum[tid]);
}

// 7) summaries /= N
__global__ void k_scale(float* __restrict__ out_sum) {
    int i = threadIdx.x;
    if (i < RR * FOUT) out_sum[i] *= (1.0f / NN);
}

// ---------------- launch ----------------------------------------------------
extern "C" void kernel_launch(void* const* d_in, const int* in_sizes, int n_in,
                              void* d_out, int out_size) {
    const float* x     = (const float*)d_in[0];
    const int*   ei    = (const int*)d_in[1];
    const int*   perms = (const int*)d_in[2];
    const float* Ws    = (const float*)d_in[3];
    const float* bs    = (const float*)d_in[4];

    float* out = (float*)d_out;
    float* out_pos = out;
    float* out_neg = out + (size_t)RR * NN * FOUT;
    float* out_sum = out + (size_t)2 * RR * NN * FOUT;

    cudaFuncSetAttribute(k_gemm, cudaFuncAttributeMaxDynamicSharedMemorySize, GEMM_SMEM);

    k_init<<<(M_ROWS + 255) / 256, 256>>>(out_sum);
    k_count<<<(RR * EE + 255) / 256, 256>>>(ei);
    k_dinv<<<(M_ROWS + 255) / 256, 256>>>();
    k_scan1<<<SCAN_NB, 512>>>();
    k_scan2<<<1, 256>>>(SCAN_NB);
    k_scan3<<<(M_ROWS + 255) / 256, 256>>>();
    k_fill<<<(RR * EE + 255) / 256, 256>>>(ei);
    k_gemm<<<dim3((NN + GT_M - 1) / GT_M, RR), 256, GEMM_SMEM>>>(x, Ws);
    k_gather<<<dim3(GB, RR), 256>>>(perms, bs, out_pos, out_neg, out_sum);
    k_scale<<<1, 256>>>(out_sum);
}

// round 4
// speedup vs baseline: 1.7886x; 1.0247x over previous
#include <cuda_runtime.h>
#include <cuda_bf16.h>
#include <cstdint>

#define NN 100000
#define EE 600000
#define RR 3
#define FIN 128
#define FOUT 64
#define M_ROWS (RR * NN)          // 300000

// ---------------- scratch (device globals; no allocation allowed) ----------
__device__ float g_hw[(size_t)RR * NN * FOUT];   // x @ W per relation (76.8 MB)
__device__ float g_dinv[M_ROWS];
__device__ int   g_cnt[M_ROWS];                  // in-degree (edges only)
__device__ int   g_cur[M_ROWS];                  // fill cursors
__device__ int   g_off[M_ROWS];                  // per-block exclusive scan
__device__ int   g_csr_src[RR * EE];             // CSR source ids
__device__ int   g_part[256];                    // scan block partials
// W bf16 split images, layout [img 6][n 64][kpair 68(pad)] words; img = rel*2 + (0=hi,1=lo)
__device__ __align__(16) uint32_t g_wimg[6 * 64 * 68];

__device__ __forceinline__ uint32_t bf16_split_pack(float a, float b, uint32_t& lo_pack) {
    __nv_bfloat16 ha = __float2bfloat16_rn(a);
    __nv_bfloat16 hb = __float2bfloat16_rn(b);
    __nv_bfloat16 la = __float2bfloat16_rn(a - __bfloat162float(ha));
    __nv_bfloat16 lb = __float2bfloat16_rn(b - __bfloat162float(hb));
    lo_pack = (uint32_t)__bfloat16_as_ushort(la) | ((uint32_t)__bfloat16_as_ushort(lb) << 16);
    return (uint32_t)__bfloat16_as_ushort(ha) | ((uint32_t)__bfloat16_as_ushort(hb) << 16);
}

__device__ __forceinline__ void mma_bf16(float* c, uint32_t a0, uint32_t a1, uint32_t a2, uint32_t a3,
                                         uint32_t b0, uint32_t b1) {
    asm volatile("mma.sync.aligned.m16n8k16.row.col.f32.bf16.bf16.f32 "
                 "{%0,%1,%2,%3}, {%4,%5,%6,%7}, {%8,%9}, {%0,%1,%2,%3};"
                 : "+f"(c[0]), "+f"(c[1]), "+f"(c[2]), "+f"(c[3])
                 : "r"(a0), "r"(a1), "r"(a2), "r"(a3), "r"(b0), "r"(b1));
}

// 1) zero counts, cursors, summary
__global__ void k_init(float* __restrict__ out_sum) {
    int i = blockIdx.x * blockDim.x + threadIdx.x;
    if (i < M_ROWS) { g_cnt[i] = 0; g_cur[i] = 0; }
    if (i < RR * FOUT) out_sum[i] = 0.0f;
}

// 2) count in-degrees over dst
__global__ void k_count(const int* __restrict__ ei) {
    int i = blockIdx.x * blockDim.x + threadIdx.x;
    if (i >= RR * EE) return;
    int r = i / EE, e = i - r * EE;
    int d = ei[(size_t)r * 2 * EE + EE + e];
    atomicAdd(&g_cnt[r * NN + d], 1);
}

// ---- exclusive scan of g_cnt -> g_off (block-local) + fused dinv -----------
#define SCAN_NB ((M_ROWS + 2047) / 2048)
__global__ void k_scan1() {
    __shared__ int sh[512];
    int b = blockIdx.x, tid = threadIdx.x;
    int base = b * 2048 + tid * 4;
    int v[4], s = 0;
#pragma unroll
    for (int j = 0; j < 4; j++) {
        int idx = base + j;
        v[j] = (idx < M_ROWS) ? g_cnt[idx] : 0;
        s += v[j];
        if (idx < M_ROWS) g_dinv[idx] = rsqrtf((float)(v[j] + 1));   // fused dinv
    }
    sh[tid] = s; __syncthreads();
    for (int o = 1; o < 512; o <<= 1) {
        int t = (tid >= o) ? sh[tid - o] : 0;
        __syncthreads();
        sh[tid] += t;
        __syncthreads();
    }
    int run = sh[tid] - s;
#pragma unroll
    for (int j = 0; j < 4; j++) { int idx = base + j; if (idx < M_ROWS) g_off[idx] = run; run += v[j]; }
    if (tid == 511) g_part[b] = sh[511];
}
__global__ void k_scan2(int n) {
    __shared__ int sh[256];
    int tid = threadIdx.x;
    int v = (tid < n) ? g_part[tid] : 0;
    sh[tid] = v; __syncthreads();
    for (int o = 1; o < 256; o <<= 1) {
        int t = (tid >= o) ? sh[tid - o] : 0;
        __syncthreads();
        sh[tid] += t;
        __syncthreads();
    }
    if (tid < n) g_part[tid] = sh[tid] - v;
}

// 4) fill CSR (adds scan partial inline)
__global__ void k_fill(const int* __restrict__ ei) {
    int i = blockIdx.x * blockDim.x + threadIdx.x;
    if (i >= RR * EE) return;
    int r = i / EE, e = i - r * EE;
    const int* base = ei + (size_t)r * 2 * EE;
    int s = base[e];
    int d = base[EE + e];
    int g = r * NN + d;
    int p = g_off[g] + g_part[g >> 11] + atomicAdd(&g_cur[g], 1);
    g_csr_src[p] = s;
}

// 5a) convert W into bf16 hi/lo images (B layout: [n][kpair], pitch 68 words)
__global__ void k_wconv(const float* __restrict__ Ws) {
    int idx = blockIdx.x * blockDim.x + threadIdx.x;    // (r, n, kpair)
    if (idx >= RR * 64 * 64) return;
    int r = idx >> 12, rem = idx & 4095, n = rem >> 6, kp = rem & 63;
    const float* W = Ws + (size_t)r * FIN * FOUT;
    float w0 = W[(2 * kp) * FOUT + n];
    float w1 = W[(2 * kp + 1) * FOUT + n];
    uint32_t lp, hp = bf16_split_pack(w0, w1, lp);
    g_wimg[(r * 2 + 0) * (64 * 68) + n * 68 + kp] = hp;
    g_wimg[(r * 2 + 1) * (64 * 68) + n * 68 + kp] = lp;
}

// 5b) GEMM via mma.sync bf16 2-way split: g_hw[r] = x @ W[r] for all 3 r.
//    Block: 128 threads / 4 warps; tile 128 rows x 64 cols x K=128.
//    Warp w owns rows [w*32, w*32+32) -> 2 m-frags of m16n8k16.
//    smem pitch 68 words/row => all frag LDS conflict-free (banks 4*grp+tig).
#define A_WORDS (128 * 68)            // 8704 words = 34816 B
#define B_WORDS (64 * 68)             // 4352 words = 17408 B
#define SM_AH 0
#define SM_AL (A_WORDS * 4)           // 34816
#define SM_B  (2 * A_WORDS * 4)       // 69632
#define SMEM_MMA (SM_B + 6 * B_WORDS * 4)   // 174080
#define NB_TILES ((NN + 127) / 128)

__global__ void __launch_bounds__(128, 1) k_gemm_mma(const float* __restrict__ x) {
    extern __shared__ char smem[];
    uint32_t* sAH = (uint32_t*)(smem + SM_AH);
    uint32_t* sAL = (uint32_t*)(smem + SM_AL);
    uint32_t* sB  = (uint32_t*)(smem + SM_B);

    const int tid = threadIdx.x;
    const int row0 = blockIdx.x * 128;
    const int nrows = min(128, NN - row0);

    // stage W images (6 x 17408 B, L2-resident)
    {
        const uint4* src = (const uint4*)g_wimg;
        uint4* dst = (uint4*)sB;
        for (int i = tid; i < 6 * B_WORDS / 4; i += 128) dst[i] = src[i];
    }
    // convert x tile -> A_hi / A_lo bf16 (zero-pad past nrows)
    for (int i = tid; i < 128 * 64; i += 128) {
        int row = i >> 6, kp = i & 63;
        float2 v = make_float2(0.f, 0.f);
        if (row < nrows) v = *(const float2*)(x + (size_t)(row0 + row) * FIN + kp * 2);
        uint32_t lp, hp = bf16_split_pack(v.x, v.y, lp);
        sAH[row * 68 + kp] = hp;
        sAL[row * 68 + kp] = lp;
    }
    __syncthreads();

    const int w = tid >> 5, lane = tid & 31;
    const int grp = lane >> 2, tig = lane & 3;
    const int rbase = w * 32;

    for (int rel = 0; rel < RR; rel++) {
        float acc[2][8][4];
#pragma unroll
        for (int mf = 0; mf < 2; mf++)
#pragma unroll
            for (int nf = 0; nf < 8; nf++)
#pragma unroll
                for (int q = 0; q < 4; q++) acc[mf][nf][q] = 0.0f;

        for (int prod = 0; prod < 3; prod++) {
            const uint32_t* aImg = (prod == 2) ? sAL : sAH;
            const uint32_t* bImg = sB + (rel * 2 + (prod == 1 ? 1 : 0)) * B_WORDS;
#pragma unroll
            for (int ks = 0; ks < 8; ks++) {
                uint32_t b0[8], b1[8];
#pragma unroll
                for (int nf = 0; nf < 8; nf++) {
                    int bw = (nf * 8 + grp) * 68 + ks * 8 + tig;
                    b0[nf] = bImg[bw];
                    b1[nf] = bImg[bw + 4];
                }
#pragma unroll
                for (int mf = 0; mf < 2; mf++) {
                    int aw = (rbase + mf * 16 + grp) * 68 + ks * 8 + tig;
                    uint32_t a0 = aImg[aw];
                    uint32_t a1 = aImg[aw + 8 * 68];
                    uint32_t a2 = aImg[aw + 4];
                    uint32_t a3 = aImg[aw + 8 * 68 + 4];
#pragma unroll
                    for (int nf = 0; nf < 8; nf++)
                        mma_bf16(acc[mf][nf], a0, a1, a2, a3, b0[nf], b1[nf]);
                }
            }
        }

        float* dstR = g_hw + ((size_t)rel * NN + row0) * FOUT;
#pragma unroll
        for (int mf = 0; mf < 2; mf++) {
            int rr = rbase + mf * 16 + grp;
#pragma unroll
            for (int nf = 0; nf < 8; nf++) {
                int col = nf * 8 + tig * 2;
                if (rr < nrows)
                    *(float2*)(dstR + (size_t)rr * FOUT + col) = make_float2(acc[mf][nf][0], acc[mf][nf][1]);
                if (rr + 8 < nrows)
                    *(float2*)(dstR + (size_t)(rr + 8) * FOUT + col) = make_float2(acc[mf][nf][2], acc[mf][nf][3]);
            }
        }
    }
}

// 6) fused gather
#define GB 1024
__global__ void __launch_bounds__(256) k_gather(const int* __restrict__ perms,
                                                const float* __restrict__ bs,
                                                float* __restrict__ out_pos,
                                                float* __restrict__ out_neg,
                                                float* __restrict__ out_sum) {
    __shared__ float ssum[FOUT];
    const int r = blockIdx.y;
    const int tid = threadIdx.x;
    if (tid < FOUT) ssum[tid] = 0.0f;
    __syncthreads();

    const int wid = tid >> 5, lane = tid & 31;
    const int half = lane >> 4, l = lane & 15;
    const float* hwr = g_hw + (size_t)r * NN * FOUT;
    float* outb = half ? out_neg : out_pos;
    const float4 b4 = *(const float4*)(bs + r * FOUT + l * 4);

    float4 asum = make_float4(0.f, 0.f, 0.f, 0.f);

    for (int row = blockIdx.x * 8 + wid; row < NN; row += GB * 8) {
        int g = r * NN + row;
        float dd = g_dinv[g];
        int self_s = half ? perms[g] : row;
        float4 v = *(const float4*)(hwr + (size_t)self_s * FOUT + l * 4);
        float w0 = dd * dd;
        float4 acc = make_float4(v.x * w0, v.y * w0, v.z * w0, v.w * w0);

        int beg = g_off[g] + g_part[g >> 11];
        int end = beg + g_cnt[g];
        for (int e = beg; e < end; e++) {
            int s = g_csr_src[e];
            float w = g_dinv[r * NN + s] * dd;
            int src2 = half ? perms[r * NN + s] : s;
            float4 u = *(const float4*)(hwr + (size_t)src2 * FOUT + l * 4);
            acc.x += u.x * w; acc.y += u.y * w; acc.z += u.z * w; acc.w += u.w * w;
        }
        acc.x = fmaxf(acc.x + b4.x, 0.0f);
        acc.y = fmaxf(acc.y + b4.y, 0.0f);
        acc.z = fmaxf(acc.z + b4.z, 0.0f);
        acc.w = fmaxf(acc.w + b4.w, 0.0f);
        *(float4*)(outb + (size_t)g * FOUT + l * 4) = acc;
        if (!half) {
            asum.x += acc.x; asum.y += acc.y; asum.z += acc.z; asum.w += acc.w;
        }
    }
    if (!half) {
        atomicAdd(&ssum[l * 4 + 0], asum.x);
        atomicAdd(&ssum[l * 4 + 1], asum.y);
        atomicAdd(&ssum[l * 4 + 2], asum.z);
        atomicAdd(&ssum[l * 4 + 3], asum.w);
    }
    __syncthreads();
    if (tid < FOUT) atomicAdd(&out_sum[r * FOUT + tid], ssum[tid]);
}

// 7) summaries /= N
__global__ void k_scale(float* __restrict__ out_sum) {
    int i = threadIdx.x;
    if (i < RR * FOUT) out_sum[i] *= (1.0f / NN);
}

// ---------------- launch ----------------------------------------------------
extern "C" void kernel_launch(void* const* d_in, const int* in_sizes, int n_in,
                              void* d_out, int out_size) {
    const float* x     = (const float*)d_in[0];
    const int*   ei    = (const int*)d_in[1];
    const int*   perms = (const int*)d_in[2];
    const float* Ws    = (const float*)d_in[3];
    const float* bs    = (const float*)d_in[4];

    float* out = (float*)d_out;
    float* out_pos = out;
    float* out_neg = out + (size_t)RR * NN * FOUT;
    float* out_sum = out + (size_t)2 * RR * NN * FOUT;

    cudaFuncSetAttribute(k_gemm_mma, cudaFuncAttributeMaxDynamicSharedMemorySize, SMEM_MMA);

    k_init<<<(M_ROWS + 255) / 256, 256>>>(out_sum);
    k_count<<<(RR * EE + 255) / 256, 256>>>(ei);
    k_wconv<<<(RR * 64 * 64 + 255) / 256, 256>>>(Ws);
    k_scan1<<<SCAN_NB, 512>>>();
    k_scan2<<<1, 256>>>(SCAN_NB);
    k_fill<<<(RR * EE + 255) / 256, 256>>>(ei);
    k_gemm_mma<<<NB_TILES, 128, SMEM_MMA>>>(x);
    k_gather<<<dim3(GB, RR), 256>>>(perms, bs, out_pos, out_neg, out_sum);
    k_scale<<<1, 256>>>(out_sum);
}